// round 8
// baseline (speedup 1.0000x reference)
#include <cuda_runtime.h>
#include <cuda_fp16.h>
#include <cstdint>

#define N_NODES 100000
#define N_EDGES 1600000
#define IN_F 64
#define OUT_F 64
#define SUPPORT 3

#define M_BINS (SUPPORT * N_NODES)                 // 300000 (k,row) bins
#define TOT_E  (SUPPORT * N_EDGES)                 // 4.8M edges
#define SCAN_BS 1024
#define NBLK ((M_BINS + SCAN_BS - 1) / SCAN_BS)    // 293

// ---- static scratch (no runtime allocation) -------------------------------
__device__ __half             g_Xh[(size_t)N_NODES * IN_F];           // 12.8 MB fp16 X
__device__ __half             g_Yh[(size_t)M_BINS * IN_F];            // 38.4 MB fp16 Y
__device__ int                g_count[M_BINS];
__device__ int                g_start[M_BINS + 1];
__device__ int                g_cursor[M_BINS];
__device__ int                g_partial[SCAN_BS];
__device__ unsigned long long g_pairs[TOT_E];      // (val<<32 | col), bin-sorted

// ---------------------------------------------------------------------------
// X (fp32) -> g_Xh (fp16). 4 floats per thread.
// ---------------------------------------------------------------------------
__global__ __launch_bounds__(256) void prep_kernel(const float* __restrict__ X) {
    int i = blockIdx.x * 256 + threadIdx.x;            // float4 index
    if (i >= N_NODES * IN_F / 4) return;
    float4 v = reinterpret_cast<const float4*>(X)[i];
    __half2 h0 = __floats2half2_rn(v.x, v.y);
    __half2 h1 = __floats2half2_rn(v.z, v.w);
    uint2 pk = make_uint2(*reinterpret_cast<unsigned int*>(&h0),
                          *reinterpret_cast<unsigned int*>(&h1));
    reinterpret_cast<uint2*>(g_Xh)[i] = pk;
}

// ---------------------------------------------------------------------------
// Counting sort by (support, destination row)
// ---------------------------------------------------------------------------
__global__ __launch_bounds__(256) void zero_kernel() {
    int i = blockIdx.x * 256 + threadIdx.x;
    if (i < M_BINS) g_count[i] = 0;
}

__global__ __launch_bounds__(256) void hist_kernel(const int* __restrict__ rows) {
    int g = blockIdx.x * 256 + threadIdx.x;
    if (g >= TOT_E / 4) return;
    int  e0 = g * 4;
    int  k  = e0 / N_EDGES;
    int4 r4 = *reinterpret_cast<const int4*>(rows + e0);
    int  kb = k * N_NODES;
    atomicAdd(&g_count[kb + r4.x], 1);
    atomicAdd(&g_count[kb + r4.y], 1);
    atomicAdd(&g_count[kb + r4.z], 1);
    atomicAdd(&g_count[kb + r4.w], 1);
}

__global__ __launch_bounds__(SCAN_BS) void scanA_kernel() {
    __shared__ int s[SCAN_BS];
    int t = threadIdx.x;
    int i = blockIdx.x * SCAN_BS + t;
    int v = (i < M_BINS) ? g_count[i] : 0;
    s[t] = v;
    __syncthreads();
    #pragma unroll
    for (int off = 1; off < SCAN_BS; off <<= 1) {
        int x = (t >= off) ? s[t - off] : 0;
        __syncthreads();
        s[t] += x;
        __syncthreads();
    }
    if (i < M_BINS) g_start[i] = s[t] - v;
    if (t == SCAN_BS - 1) g_partial[blockIdx.x] = s[t];
}

// scanC: each block reduces partials[0..bid) itself.
__global__ __launch_bounds__(SCAN_BS) void scanC_kernel() {
    __shared__ int s[SCAN_BS];
    int t = threadIdx.x;
    int v = (t < (int)blockIdx.x && t < NBLK) ? g_partial[t] : 0;
    s[t] = v;
    __syncthreads();
    #pragma unroll
    for (int off = SCAN_BS / 2; off > 0; off >>= 1) {
        if (t < off) s[t] += s[t + off];
        __syncthreads();
    }
    int prefix = s[0];

    int i = blockIdx.x * SCAN_BS + t;
    if (i < M_BINS) {
        int st = g_start[i] + prefix;
        g_start[i]  = st;
        g_cursor[i] = st;
    }
    if (blockIdx.x == 0 && t == 0) g_start[M_BINS] = TOT_E;
}

__global__ __launch_bounds__(256) void scatter_kernel(const int* __restrict__ rows,
                                                      const int* __restrict__ cols,
                                                      const float* __restrict__ vals) {
    int g = blockIdx.x * 256 + threadIdx.x;
    if (g >= TOT_E / 4) return;
    int    e0 = g * 4;
    int    k  = e0 / N_EDGES;
    int4   r4 = *reinterpret_cast<const int4*>(rows + e0);
    int4   c4 = *reinterpret_cast<const int4*>(cols + e0);
    float4 v4 = *reinterpret_cast<const float4*>(vals + e0);
    int    kb = k * N_NODES;

    int p0 = atomicAdd(&g_cursor[kb + r4.x], 1);
    int p1 = atomicAdd(&g_cursor[kb + r4.y], 1);
    int p2 = atomicAdd(&g_cursor[kb + r4.z], 1);
    int p3 = atomicAdd(&g_cursor[kb + r4.w], 1);

    g_pairs[p0] = ((unsigned long long)__float_as_uint(v4.x) << 32) | (unsigned int)c4.x;
    g_pairs[p1] = ((unsigned long long)__float_as_uint(v4.y) << 32) | (unsigned int)c4.y;
    g_pairs[p2] = ((unsigned long long)__float_as_uint(v4.z) << 32) | (unsigned int)c4.z;
    g_pairs[p3] = ((unsigned long long)__float_as_uint(v4.w) << 32) | (unsigned int)c4.w;
}

// ---------------------------------------------------------------------------
// SpMM accumulate: one warp per (k,node) bin (300K warps).
// Pairs loaded coalesced (one 256B request per <=32 edges), shfl-broadcast;
// gathers then issue with deep MLP. fp32 accumulation, fp16 output.
// ---------------------------------------------------------------------------
__global__ __launch_bounds__(256) void accum_kernel() {
    int t    = blockIdx.x * 256 + threadIdx.x;
    int bin  = t >> 5;
    int lane = t & 31;
    if (bin >= M_BINS) return;

    int e0 = __ldg(&g_start[bin]);
    int e1 = __ldg(&g_start[bin + 1]);

    float2 acc = make_float2(0.f, 0.f);

    for (int base = e0; base < e1; base += 32) {
        int cnt = e1 - base;
        if (cnt > 32) cnt = 32;

        unsigned long long pk = 0;
        if (lane < cnt) pk = __ldg(g_pairs + base + lane);

        #pragma unroll 4
        for (int j = 0; j < cnt; j++) {
            unsigned long long p = __shfl_sync(0xffffffffu, pk, j);
            __half2 h = *reinterpret_cast<const __half2*>(
                g_Xh + (size_t)(unsigned int)p * IN_F + lane * 2);
            float  v = __uint_as_float((unsigned int)(p >> 32));
            float2 f = __half22float2(h);
            acc.x += v * f.x;
            acc.y += v * f.y;
        }
    }

    __half2 ho = __floats2half2_rn(acc.x, acc.y);
    *reinterpret_cast<__half2*>(g_Yh + (size_t)bin * IN_F + lane * 2) = ho;
}

// ---------------------------------------------------------------------------
// Fused GEMM: out[n][:] = bias + sum_k Yh[k][n][:] @ W[k*64:(k+1)*64][:]
// ---------------------------------------------------------------------------
__global__ __launch_bounds__(256) void gemm_kernel(const float* __restrict__ W,
                                                   const float* __restrict__ bias,
                                                   float* __restrict__ out) {
    __shared__ float4 Ys4[64][16];    // [row][j/4] fp32
    __shared__ float4 Ws4[64][16];    // [j][col/4]

    const int rbase = blockIdx.x * 64;
    const int tid   = threadIdx.x;
    const int ty    = tid >> 4;
    const int tx    = tid & 15;

    float acc[4][4];
    #pragma unroll
    for (int i = 0; i < 4; i++)
        #pragma unroll
        for (int c = 0; c < 4; c++) acc[i][c] = 0.f;

    for (int k = 0; k < SUPPORT; k++) {
        const __half* Yk = g_Yh + (size_t)k * N_NODES * IN_F;
        #pragma unroll
        for (int i = tid; i < 64 * 16; i += 256) {
            int r  = i >> 4;
            int c4 = i & 15;
            int gr = rbase + r;
            float4 v = make_float4(0.f, 0.f, 0.f, 0.f);
            if (gr < N_NODES) {
                uint2 pk = *reinterpret_cast<const uint2*>(Yk + (size_t)gr * IN_F + c4 * 4);
                float2 lo = __half22float2(*reinterpret_cast<__half2*>(&pk.x));
                float2 hi = __half22float2(*reinterpret_cast<__half2*>(&pk.y));
                v = make_float4(lo.x, lo.y, hi.x, hi.y);
            }
            Ys4[r][c4] = v;
        }
        #pragma unroll
        for (int i = tid; i < 64 * 16; i += 256) {
            int j  = i >> 4;
            int c4 = i & 15;
            Ws4[j][c4] = *reinterpret_cast<const float4*>(W + (size_t)(k * 64 + j) * OUT_F + c4 * 4);
        }
        __syncthreads();

        #pragma unroll
        for (int j0 = 0; j0 < 64; j0 += 4) {
            float4 b0 = Ws4[j0 + 0][tx];
            float4 b1 = Ws4[j0 + 1][tx];
            float4 b2 = Ws4[j0 + 2][tx];
            float4 b3 = Ws4[j0 + 3][tx];
            #pragma unroll
            for (int i = 0; i < 4; i++) {
                float4 a = Ys4[ty * 4 + i][j0 >> 2];
                acc[i][0] += a.x * b0.x + a.y * b1.x + a.z * b2.x + a.w * b3.x;
                acc[i][1] += a.x * b0.y + a.y * b1.y + a.z * b2.y + a.w * b3.y;
                acc[i][2] += a.x * b0.z + a.y * b1.z + a.z * b2.z + a.w * b3.z;
                acc[i][3] += a.x * b0.w + a.y * b1.w + a.z * b2.w + a.w * b3.w;
            }
        }
        __syncthreads();
    }

    float4 b4 = *reinterpret_cast<const float4*>(bias + tx * 4);
    #pragma unroll
    for (int i = 0; i < 4; i++) {
        int gr = rbase + ty * 4 + i;
        if (gr < N_NODES) {
            float4 o = make_float4(acc[i][0] + b4.x, acc[i][1] + b4.y,
                                   acc[i][2] + b4.z, acc[i][3] + b4.w);
            *reinterpret_cast<float4*>(out + (size_t)gr * OUT_F + tx * 4) = o;
        }
    }
}

// ---------------------------------------------------------------------------
extern "C" void kernel_launch(void* const* d_in, const int* in_sizes, int n_in,
                              void* d_out, int out_size) {
    const float* X     = (const float*)d_in[0];
    const int*   erows = (const int*)  d_in[1];
    const int*   ecols = (const int*)  d_in[2];
    const float* evals = (const float*)d_in[3];
    const float* W     = (const float*)d_in[4];
    const float* bias  = (const float*)d_in[5];
    float*       out   = (float*)d_out;

    prep_kernel<<<(N_NODES * IN_F / 4 + 255) / 256, 256>>>(X);

    int ebl4 = (TOT_E / 4 + 255) / 256;
    zero_kernel<<<(M_BINS + 255) / 256, 256>>>();
    hist_kernel<<<ebl4, 256>>>(erows);
    scanA_kernel<<<NBLK, SCAN_BS>>>();
    scanC_kernel<<<NBLK, SCAN_BS>>>();
    scatter_kernel<<<ebl4, 256>>>(erows, ecols, evals);

    // Y[bin] = S_k @ Xh rows; warp per bin
    int ablocks = ((M_BINS * 32) + 255) / 256;
    accum_kernel<<<ablocks, 256>>>();

    // out = concat_k(Y_k) @ W + bias
    gemm_kernel<<<(N_NODES + 63) / 64, 256>>>(W, bias, out);
}

// round 9
// speedup vs baseline: 1.0293x; 1.0293x over previous
#include <cuda_runtime.h>
#include <cuda_fp16.h>
#include <cstdint>

#define N_NODES 100000
#define N_EDGES 1600000
#define IN_F 64
#define OUT_F 64
#define SUPPORT 3

#define M_BINS (SUPPORT * N_NODES)                 // 300000 (k,row) bins
#define TOT_E  (SUPPORT * N_EDGES)                 // 4.8M edges
#define SCAN_BS 1024
#define NBLK ((M_BINS + SCAN_BS - 1) / SCAN_BS)    // 293

// ---- static scratch (no runtime allocation) -------------------------------
__device__ __half             g_Xh[(size_t)N_NODES * IN_F];           // 12.8 MB fp16 X
__device__ __half             g_Yh[(size_t)M_BINS * IN_F];            // 38.4 MB fp16 Y
__device__ int                g_count[M_BINS];
__device__ int                g_start[M_BINS + 1];
__device__ int                g_cursor[M_BINS];
__device__ int                g_partial[SCAN_BS];
__device__ unsigned long long g_pairs[TOT_E];      // (val<<32 | col), bin-sorted

// ---------------------------------------------------------------------------
// X (fp32) -> g_Xh (fp16). 4 floats per thread.
// ---------------------------------------------------------------------------
__global__ __launch_bounds__(256) void prep_kernel(const float* __restrict__ X) {
    int i = blockIdx.x * 256 + threadIdx.x;            // float4 index
    if (i >= N_NODES * IN_F / 4) return;
    float4 v = reinterpret_cast<const float4*>(X)[i];
    __half2 h0 = __floats2half2_rn(v.x, v.y);
    __half2 h1 = __floats2half2_rn(v.z, v.w);
    uint2 pk = make_uint2(*reinterpret_cast<unsigned int*>(&h0),
                          *reinterpret_cast<unsigned int*>(&h1));
    reinterpret_cast<uint2*>(g_Xh)[i] = pk;
}

// ---------------------------------------------------------------------------
// Counting sort by (support, destination row)
// ---------------------------------------------------------------------------
__global__ __launch_bounds__(256) void zero_kernel() {
    int i = blockIdx.x * 256 + threadIdx.x;
    if (i < M_BINS) g_count[i] = 0;
}

__global__ __launch_bounds__(256) void hist_kernel(const int* __restrict__ rows) {
    int g = blockIdx.x * 256 + threadIdx.x;
    if (g >= TOT_E / 4) return;
    int  e0 = g * 4;
    int  k  = e0 / N_EDGES;
    int4 r4 = *reinterpret_cast<const int4*>(rows + e0);
    int  kb = k * N_NODES;
    atomicAdd(&g_count[kb + r4.x], 1);
    atomicAdd(&g_count[kb + r4.y], 1);
    atomicAdd(&g_count[kb + r4.z], 1);
    atomicAdd(&g_count[kb + r4.w], 1);
}

__global__ __launch_bounds__(SCAN_BS) void scanA_kernel() {
    __shared__ int s[SCAN_BS];
    int t = threadIdx.x;
    int i = blockIdx.x * SCAN_BS + t;
    int v = (i < M_BINS) ? g_count[i] : 0;
    s[t] = v;
    __syncthreads();
    #pragma unroll
    for (int off = 1; off < SCAN_BS; off <<= 1) {
        int x = (t >= off) ? s[t - off] : 0;
        __syncthreads();
        s[t] += x;
        __syncthreads();
    }
    if (i < M_BINS) g_start[i] = s[t] - v;
    if (t == SCAN_BS - 1) g_partial[blockIdx.x] = s[t];
}

// scanC: each block reduces partials[0..bid) itself.
__global__ __launch_bounds__(SCAN_BS) void scanC_kernel() {
    __shared__ int s[SCAN_BS];
    int t = threadIdx.x;
    int v = (t < (int)blockIdx.x && t < NBLK) ? g_partial[t] : 0;
    s[t] = v;
    __syncthreads();
    #pragma unroll
    for (int off = SCAN_BS / 2; off > 0; off >>= 1) {
        if (t < off) s[t] += s[t + off];
        __syncthreads();
    }
    int prefix = s[0];

    int i = blockIdx.x * SCAN_BS + t;
    if (i < M_BINS) {
        int st = g_start[i] + prefix;
        g_start[i]  = st;
        g_cursor[i] = st;
    }
    if (blockIdx.x == 0 && t == 0) g_start[M_BINS] = TOT_E;
}

__global__ __launch_bounds__(256) void scatter_kernel(const int* __restrict__ rows,
                                                      const int* __restrict__ cols,
                                                      const float* __restrict__ vals) {
    int g = blockIdx.x * 256 + threadIdx.x;
    if (g >= TOT_E / 4) return;
    int    e0 = g * 4;
    int    k  = e0 / N_EDGES;
    int4   r4 = *reinterpret_cast<const int4*>(rows + e0);
    int4   c4 = *reinterpret_cast<const int4*>(cols + e0);
    float4 v4 = *reinterpret_cast<const float4*>(vals + e0);
    int    kb = k * N_NODES;

    int p0 = atomicAdd(&g_cursor[kb + r4.x], 1);
    int p1 = atomicAdd(&g_cursor[kb + r4.y], 1);
    int p2 = atomicAdd(&g_cursor[kb + r4.z], 1);
    int p3 = atomicAdd(&g_cursor[kb + r4.w], 1);

    g_pairs[p0] = ((unsigned long long)__float_as_uint(v4.x) << 32) | (unsigned int)c4.x;
    g_pairs[p1] = ((unsigned long long)__float_as_uint(v4.y) << 32) | (unsigned int)c4.y;
    g_pairs[p2] = ((unsigned long long)__float_as_uint(v4.z) << 32) | (unsigned int)c4.z;
    g_pairs[p3] = ((unsigned long long)__float_as_uint(v4.w) << 32) | (unsigned int)c4.w;
}

// ---------------------------------------------------------------------------
// SpMM accumulate: one warp per node. The 3 support bins are processed in an
// INTERLEAVED main loop: up to three independent 4-edge steps in flight per
// iteration (MLP up to 12 gathers + 12 pairs loads). All predicates are
// warp-uniform (lanes share the bin), so no divergence. fp32 accumulation,
// fp16 output. No atomics.
// ---------------------------------------------------------------------------
__device__ __forceinline__ void step4(int e, float2& acc, int lane) {
    unsigned long long p0 = __ldg(g_pairs + e + 0);
    unsigned long long p1 = __ldg(g_pairs + e + 1);
    unsigned long long p2 = __ldg(g_pairs + e + 2);
    unsigned long long p3 = __ldg(g_pairs + e + 3);
    __half2 h0 = *reinterpret_cast<const __half2*>(g_Xh + (size_t)(unsigned int)p0 * IN_F + lane * 2);
    __half2 h1 = *reinterpret_cast<const __half2*>(g_Xh + (size_t)(unsigned int)p1 * IN_F + lane * 2);
    __half2 h2 = *reinterpret_cast<const __half2*>(g_Xh + (size_t)(unsigned int)p2 * IN_F + lane * 2);
    __half2 h3 = *reinterpret_cast<const __half2*>(g_Xh + (size_t)(unsigned int)p3 * IN_F + lane * 2);
    float2 f0 = __half22float2(h0);
    float2 f1 = __half22float2(h1);
    float2 f2 = __half22float2(h2);
    float2 f3 = __half22float2(h3);
    float v0 = __uint_as_float((unsigned int)(p0 >> 32));
    float v1 = __uint_as_float((unsigned int)(p1 >> 32));
    float v2 = __uint_as_float((unsigned int)(p2 >> 32));
    float v3 = __uint_as_float((unsigned int)(p3 >> 32));
    acc.x += v0 * f0.x; acc.y += v0 * f0.y;
    acc.x += v1 * f1.x; acc.y += v1 * f1.y;
    acc.x += v2 * f2.x; acc.y += v2 * f2.y;
    acc.x += v3 * f3.x; acc.y += v3 * f3.y;
}

__global__ __launch_bounds__(256) void accum_kernel() {
    int t    = blockIdx.x * 256 + threadIdx.x;
    int n    = t >> 5;
    int lane = t & 31;
    if (n >= N_NODES) return;

    int    e[SUPPORT], eend[SUPPORT];
    float2 acc[SUPPORT];
    #pragma unroll
    for (int k = 0; k < SUPPORT; k++) {
        e[k]    = __ldg(&g_start[k * N_NODES + n]);
        eend[k] = __ldg(&g_start[k * N_NODES + n + 1]);
        acc[k]  = make_float2(0.f, 0.f);
    }

    // Interleaved main loop: three independent 4-edge streams.
    while ((e[0] + 4 <= eend[0]) | (e[1] + 4 <= eend[1]) | (e[2] + 4 <= eend[2])) {
        #pragma unroll
        for (int k = 0; k < SUPPORT; k++) {
            if (e[k] + 4 <= eend[k]) {
                step4(e[k], acc[k], lane);
                e[k] += 4;
            }
        }
    }

    // Tails (<=3 edges per support)
    #pragma unroll
    for (int k = 0; k < SUPPORT; k++) {
        for (; e[k] < eend[k]; e[k]++) {
            unsigned long long p = __ldg(g_pairs + e[k]);
            __half2 h = *reinterpret_cast<const __half2*>(
                g_Xh + (size_t)(unsigned int)p * IN_F + lane * 2);
            float2 f = __half22float2(h);
            float  v = __uint_as_float((unsigned int)(p >> 32));
            acc[k].x += v * f.x;
            acc[k].y += v * f.y;
        }
    }

    #pragma unroll
    for (int k = 0; k < SUPPORT; k++) {
        __half2 ho = __floats2half2_rn(acc[k].x, acc[k].y);
        *reinterpret_cast<__half2*>(g_Yh + ((size_t)k * N_NODES + n) * IN_F + lane * 2) = ho;
    }
}

// ---------------------------------------------------------------------------
// Fused GEMM: out[n][:] = bias + sum_k Yh[k][n][:] @ W[k*64:(k+1)*64][:]
// ---------------------------------------------------------------------------
__global__ __launch_bounds__(256) void gemm_kernel(const float* __restrict__ W,
                                                   const float* __restrict__ bias,
                                                   float* __restrict__ out) {
    __shared__ float4 Ys4[64][16];    // [row][j/4] fp32
    __shared__ float4 Ws4[64][16];    // [j][col/4]

    const int rbase = blockIdx.x * 64;
    const int tid   = threadIdx.x;
    const int ty    = tid >> 4;
    const int tx    = tid & 15;

    float acc[4][4];
    #pragma unroll
    for (int i = 0; i < 4; i++)
        #pragma unroll
        for (int c = 0; c < 4; c++) acc[i][c] = 0.f;

    for (int k = 0; k < SUPPORT; k++) {
        const __half* Yk = g_Yh + (size_t)k * N_NODES * IN_F;
        #pragma unroll
        for (int i = tid; i < 64 * 16; i += 256) {
            int r  = i >> 4;
            int c4 = i & 15;
            int gr = rbase + r;
            float4 v = make_float4(0.f, 0.f, 0.f, 0.f);
            if (gr < N_NODES) {
                uint2 pk = *reinterpret_cast<const uint2*>(Yk + (size_t)gr * IN_F + c4 * 4);
                float2 lo = __half22float2(*reinterpret_cast<__half2*>(&pk.x));
                float2 hi = __half22float2(*reinterpret_cast<__half2*>(&pk.y));
                v = make_float4(lo.x, lo.y, hi.x, hi.y);
            }
            Ys4[r][c4] = v;
        }
        #pragma unroll
        for (int i = tid; i < 64 * 16; i += 256) {
            int j  = i >> 4;
            int c4 = i & 15;
            Ws4[j][c4] = *reinterpret_cast<const float4*>(W + (size_t)(k * 64 + j) * OUT_F + c4 * 4);
        }
        __syncthreads();

        #pragma unroll
        for (int j0 = 0; j0 < 64; j0 += 4) {
            float4 b0 = Ws4[j0 + 0][tx];
            float4 b1 = Ws4[j0 + 1][tx];
            float4 b2 = Ws4[j0 + 2][tx];
            float4 b3 = Ws4[j0 + 3][tx];
            #pragma unroll
            for (int i = 0; i < 4; i++) {
                float4 a = Ys4[ty * 4 + i][j0 >> 2];
                acc[i][0] += a.x * b0.x + a.y * b1.x + a.z * b2.x + a.w * b3.x;
                acc[i][1] += a.x * b0.y + a.y * b1.y + a.z * b2.y + a.w * b3.y;
                acc[i][2] += a.x * b0.z + a.y * b1.z + a.z * b2.z + a.w * b3.z;
                acc[i][3] += a.x * b0.w + a.y * b1.w + a.z * b2.w + a.w * b3.w;
            }
        }
        __syncthreads();
    }

    float4 b4 = *reinterpret_cast<const float4*>(bias + tx * 4);
    #pragma unroll
    for (int i = 0; i < 4; i++) {
        int gr = rbase + ty * 4 + i;
        if (gr < N_NODES) {
            float4 o = make_float4(acc[i][0] + b4.x, acc[i][1] + b4.y,
                                   acc[i][2] + b4.z, acc[i][3] + b4.w);
            *reinterpret_cast<float4*>(out + (size_t)gr * OUT_F + tx * 4) = o;
        }
    }
}

// ---------------------------------------------------------------------------
extern "C" void kernel_launch(void* const* d_in, const int* in_sizes, int n_in,
                              void* d_out, int out_size) {
    const float* X     = (const float*)d_in[0];
    const int*   erows = (const int*)  d_in[1];
    const int*   ecols = (const int*)  d_in[2];
    const float* evals = (const float*)d_in[3];
    const float* W     = (const float*)d_in[4];
    const float* bias  = (const float*)d_in[5];
    float*       out   = (float*)d_out;

    prep_kernel<<<(N_NODES * IN_F / 4 + 255) / 256, 256>>>(X);

    int ebl4 = (TOT_E / 4 + 255) / 256;
    zero_kernel<<<(M_BINS + 255) / 256, 256>>>();
    hist_kernel<<<ebl4, 256>>>(erows);
    scanA_kernel<<<NBLK, SCAN_BS>>>();
    scanC_kernel<<<NBLK, SCAN_BS>>>();
    scatter_kernel<<<ebl4, 256>>>(erows, ecols, evals);

    // Y[k][n] = (S_k @ Xh)[n]; warp per node, 3 interleaved edge streams
    int ablocks = (N_NODES * 32 + 255) / 256;
    accum_kernel<<<ablocks, 256>>>();

    // out = concat_k(Y_k) @ W + bias
    gemm_kernel<<<(N_NODES + 63) / 64, 256>>>(W, bias, out);
}

// round 10
// speedup vs baseline: 1.1189x; 1.0870x over previous
#include <cuda_runtime.h>
#include <cuda_fp16.h>
#include <mma.h>
#include <cstdint>

using namespace nvcuda;

#define N_NODES 100000
#define N_EDGES 1600000
#define IN_F 64
#define OUT_F 64
#define SUPPORT 3
#define CAT_F (SUPPORT * IN_F)                     // 192

#define M_BINS (SUPPORT * N_NODES)                 // 300000 (k,row) bins
#define TOT_E  (SUPPORT * N_EDGES)                 // 4.8M edges
#define SCAN_BS 1024
#define NBLK ((M_BINS + SCAN_BS - 1) / SCAN_BS)    // 293

// ---- static scratch (no runtime allocation) -------------------------------
__device__ __half             g_Xh[(size_t)N_NODES * IN_F];            // 12.8 MB fp16 X
__device__ __half             g_Yh[(size_t)(M_BINS + 64) * IN_F];      // fp16 Y (+64 pad rows for wmma tail)
__device__ __half             g_Wh[CAT_F * OUT_F];                     // 24 KB fp16 W
__device__ int                g_count[M_BINS];
__device__ int                g_start[M_BINS + 1];
__device__ int                g_cursor[M_BINS];
__device__ int                g_partial[SCAN_BS];
__device__ unsigned long long g_pairs[TOT_E];      // (val<<32 | col), bin-sorted

// ---------------------------------------------------------------------------
// prep: X (fp32) -> g_Xh (fp16), and W (fp32) -> g_Wh (fp16).
// ---------------------------------------------------------------------------
__global__ __launch_bounds__(256) void prep_kernel(const float* __restrict__ X,
                                                   const float* __restrict__ W) {
    int i = blockIdx.x * 256 + threadIdx.x;            // float4 index
    if (i < N_NODES * IN_F / 4) {
        float4 v = reinterpret_cast<const float4*>(X)[i];
        __half2 h0 = __floats2half2_rn(v.x, v.y);
        __half2 h1 = __floats2half2_rn(v.z, v.w);
        uint2 pk = make_uint2(*reinterpret_cast<unsigned int*>(&h0),
                              *reinterpret_cast<unsigned int*>(&h1));
        reinterpret_cast<uint2*>(g_Xh)[i] = pk;
    }
    if (i < CAT_F * OUT_F / 4) {
        float4 v = reinterpret_cast<const float4*>(W)[i];
        __half2 h0 = __floats2half2_rn(v.x, v.y);
        __half2 h1 = __floats2half2_rn(v.z, v.w);
        uint2 pk = make_uint2(*reinterpret_cast<unsigned int*>(&h0),
                              *reinterpret_cast<unsigned int*>(&h1));
        reinterpret_cast<uint2*>(g_Wh)[i] = pk;
    }
}

// ---------------------------------------------------------------------------
// Counting sort by (support, destination row)
// ---------------------------------------------------------------------------
__global__ __launch_bounds__(256) void zero_kernel() {
    int i = blockIdx.x * 256 + threadIdx.x;
    if (i < M_BINS) g_count[i] = 0;
}

__global__ __launch_bounds__(256) void hist_kernel(const int* __restrict__ rows) {
    int g = blockIdx.x * 256 + threadIdx.x;
    if (g >= TOT_E / 4) return;
    int  e0 = g * 4;
    int  k  = e0 / N_EDGES;
    int4 r4 = *reinterpret_cast<const int4*>(rows + e0);
    int  kb = k * N_NODES;
    atomicAdd(&g_count[kb + r4.x], 1);
    atomicAdd(&g_count[kb + r4.y], 1);
    atomicAdd(&g_count[kb + r4.z], 1);
    atomicAdd(&g_count[kb + r4.w], 1);
}

__global__ __launch_bounds__(SCAN_BS) void scanA_kernel() {
    __shared__ int s[SCAN_BS];
    int t = threadIdx.x;
    int i = blockIdx.x * SCAN_BS + t;
    int v = (i < M_BINS) ? g_count[i] : 0;
    s[t] = v;
    __syncthreads();
    #pragma unroll
    for (int off = 1; off < SCAN_BS; off <<= 1) {
        int x = (t >= off) ? s[t - off] : 0;
        __syncthreads();
        s[t] += x;
        __syncthreads();
    }
    if (i < M_BINS) g_start[i] = s[t] - v;
    if (t == SCAN_BS - 1) g_partial[blockIdx.x] = s[t];
}

// scanC: each block reduces partials[0..bid) itself.
__global__ __launch_bounds__(SCAN_BS) void scanC_kernel() {
    __shared__ int s[SCAN_BS];
    int t = threadIdx.x;
    int v = (t < (int)blockIdx.x && t < NBLK) ? g_partial[t] : 0;
    s[t] = v;
    __syncthreads();
    #pragma unroll
    for (int off = SCAN_BS / 2; off > 0; off >>= 1) {
        if (t < off) s[t] += s[t + off];
        __syncthreads();
    }
    int prefix = s[0];

    int i = blockIdx.x * SCAN_BS + t;
    if (i < M_BINS) {
        int st = g_start[i] + prefix;
        g_start[i]  = st;
        g_cursor[i] = st;
    }
    if (blockIdx.x == 0 && t == 0) g_start[M_BINS] = TOT_E;
}

__global__ __launch_bounds__(256) void scatter_kernel(const int* __restrict__ rows,
                                                      const int* __restrict__ cols,
                                                      const float* __restrict__ vals) {
    int g = blockIdx.x * 256 + threadIdx.x;
    if (g >= TOT_E / 4) return;
    int    e0 = g * 4;
    int    k  = e0 / N_EDGES;
    int4   r4 = *reinterpret_cast<const int4*>(rows + e0);
    int4   c4 = *reinterpret_cast<const int4*>(cols + e0);
    float4 v4 = *reinterpret_cast<const float4*>(vals + e0);
    int    kb = k * N_NODES;

    int p0 = atomicAdd(&g_cursor[kb + r4.x], 1);
    int p1 = atomicAdd(&g_cursor[kb + r4.y], 1);
    int p2 = atomicAdd(&g_cursor[kb + r4.z], 1);
    int p3 = atomicAdd(&g_cursor[kb + r4.w], 1);

    g_pairs[p0] = ((unsigned long long)__float_as_uint(v4.x) << 32) | (unsigned int)c4.x;
    g_pairs[p1] = ((unsigned long long)__float_as_uint(v4.y) << 32) | (unsigned int)c4.y;
    g_pairs[p2] = ((unsigned long long)__float_as_uint(v4.z) << 32) | (unsigned int)c4.z;
    g_pairs[p3] = ((unsigned long long)__float_as_uint(v4.w) << 32) | (unsigned int)c4.w;
}

// ---------------------------------------------------------------------------
// SpMM accumulate (R7 form — best measured): one warp per node, sequential
// support bins, 4-way unrolled gathers from fp16 X. fp32 accumulation,
// fp16 output. No atomics.
// ---------------------------------------------------------------------------
__global__ __launch_bounds__(256) void accum_kernel() {
    int t    = blockIdx.x * 256 + threadIdx.x;
    int n    = t >> 5;
    int lane = t & 31;
    if (n >= N_NODES) return;

    #pragma unroll
    for (int k = 0; k < SUPPORT; k++) {
        int bin  = k * N_NODES + n;
        int e    = __ldg(&g_start[bin]);
        int eend = __ldg(&g_start[bin + 1]);

        float2 acc = make_float2(0.f, 0.f);

        for (; e + 4 <= eend; e += 4) {
            unsigned long long p0 = __ldg(g_pairs + e + 0);
            unsigned long long p1 = __ldg(g_pairs + e + 1);
            unsigned long long p2 = __ldg(g_pairs + e + 2);
            unsigned long long p3 = __ldg(g_pairs + e + 3);
            __half2 h0 = *reinterpret_cast<const __half2*>(g_Xh + (size_t)(unsigned int)p0 * IN_F + lane * 2);
            __half2 h1 = *reinterpret_cast<const __half2*>(g_Xh + (size_t)(unsigned int)p1 * IN_F + lane * 2);
            __half2 h2 = *reinterpret_cast<const __half2*>(g_Xh + (size_t)(unsigned int)p2 * IN_F + lane * 2);
            __half2 h3 = *reinterpret_cast<const __half2*>(g_Xh + (size_t)(unsigned int)p3 * IN_F + lane * 2);
            float2 f0 = __half22float2(h0);
            float2 f1 = __half22float2(h1);
            float2 f2 = __half22float2(h2);
            float2 f3 = __half22float2(h3);
            float v0 = __uint_as_float((unsigned int)(p0 >> 32));
            float v1 = __uint_as_float((unsigned int)(p1 >> 32));
            float v2 = __uint_as_float((unsigned int)(p2 >> 32));
            float v3 = __uint_as_float((unsigned int)(p3 >> 32));
            acc.x += v0 * f0.x; acc.y += v0 * f0.y;
            acc.x += v1 * f1.x; acc.y += v1 * f1.y;
            acc.x += v2 * f2.x; acc.y += v2 * f2.y;
            acc.x += v3 * f3.x; acc.y += v3 * f3.y;
        }
        for (; e < eend; e++) {
            unsigned long long p0 = __ldg(g_pairs + e);
            __half2 h0 = *reinterpret_cast<const __half2*>(g_Xh + (size_t)(unsigned int)p0 * IN_F + lane * 2);
            float2 f0 = __half22float2(h0);
            float v0 = __uint_as_float((unsigned int)(p0 >> 32));
            acc.x += v0 * f0.x; acc.y += v0 * f0.y;
        }

        __half2 ho = __floats2half2_rn(acc.x, acc.y);
        *reinterpret_cast<__half2*>(g_Yh + ((size_t)k * N_NODES + n) * IN_F + lane * 2) = ho;
    }
}

// ---------------------------------------------------------------------------
// Tensor-core GEMM: out[n][:] = bias + sum_k Yh[k][n][:] @ Wh[k*64:(k+1)*64][:]
// wmma 16x16x16 (fp16 in, fp32 acc). A/B fragments load DIRECTLY from global
// (L2-resident), so no big smem tiles and no occupancy cliff. C staged in an
// 18KB smem tile for bias add + guarded stores (handles the N_NODES tail).
// 8 warps: warp w owns m-tile (w&3), n-tiles {2*(w>>2), 2*(w>>2)+1}.
// ---------------------------------------------------------------------------
__global__ __launch_bounds__(256) void gemm_tc_kernel(const float* __restrict__ bias,
                                                      float* __restrict__ out) {
    __shared__ float Cs[64][72];               // 18.4 KB

    const int tid   = threadIdx.x;
    const int warp  = tid >> 5;
    const int rbase = blockIdx.x * 64;
    const int mt    = warp & 3;                // m-tile (16 rows)
    const int ntb   = (warp >> 2) * 2;         // first of two n-tiles

    wmma::fragment<wmma::accumulator, 16, 16, 16, float> c0, c1;
    wmma::fill_fragment(c0, 0.f);
    wmma::fill_fragment(c1, 0.f);

    const __half* arow = g_Yh;                 // base; per-support offset below
    #pragma unroll
    for (int ks = 0; ks < SUPPORT; ks++) {
        const __half* Yk = arow + (size_t)ks * N_NODES * IN_F;
        const __half* Apt = Yk + (size_t)(rbase + mt * 16) * IN_F;
        #pragma unroll
        for (int kc = 0; kc < 4; kc++) {       // 4 x 16 = 64 K per support
            wmma::fragment<wmma::matrix_a, 16, 16, 16, __half, wmma::row_major> a;
            wmma::load_matrix_sync(a, Apt + kc * 16, IN_F);

            const __half* Bpt = g_Wh + (size_t)(ks * 64 + kc * 16) * OUT_F;
            wmma::fragment<wmma::matrix_b, 16, 16, 16, __half, wmma::row_major> b0, b1;
            wmma::load_matrix_sync(b0, Bpt + ntb * 16, OUT_F);
            wmma::load_matrix_sync(b1, Bpt + (ntb + 1) * 16, OUT_F);

            wmma::mma_sync(c0, a, b0, c0);
            wmma::mma_sync(c1, a, b1, c1);
        }
    }

    wmma::store_matrix_sync(&Cs[mt * 16][ntb * 16],       c0, 72, wmma::mem_row_major);
    wmma::store_matrix_sync(&Cs[mt * 16][(ntb + 1) * 16], c1, 72, wmma::mem_row_major);
    __syncthreads();

    // bias add + guarded vectorized store
    #pragma unroll
    for (int i = tid; i < 64 * 16; i += 256) {
        int r  = i >> 4;
        int c4 = i & 15;
        int gr = rbase + r;
        if (gr < N_NODES) {
            float4 b4 = *reinterpret_cast<const float4*>(bias + c4 * 4);
            float4 o  = make_float4(Cs[r][c4 * 4 + 0] + b4.x,
                                    Cs[r][c4 * 4 + 1] + b4.y,
                                    Cs[r][c4 * 4 + 2] + b4.z,
                                    Cs[r][c4 * 4 + 3] + b4.w);
            *reinterpret_cast<float4*>(out + (size_t)gr * OUT_F + c4 * 4) = o;
        }
    }
}

// ---------------------------------------------------------------------------
extern "C" void kernel_launch(void* const* d_in, const int* in_sizes, int n_in,
                              void* d_out, int out_size) {
    const float* X     = (const float*)d_in[0];
    const int*   erows = (const int*)  d_in[1];
    const int*   ecols = (const int*)  d_in[2];
    const float* evals = (const float*)d_in[3];
    const float* W     = (const float*)d_in[4];
    const float* bias  = (const float*)d_in[5];
    float*       out   = (float*)d_out;

    prep_kernel<<<(N_NODES * IN_F / 4 + 255) / 256, 256>>>(X, W);

    int ebl4 = (TOT_E / 4 + 255) / 256;
    zero_kernel<<<(M_BINS + 255) / 256, 256>>>();
    hist_kernel<<<ebl4, 256>>>(erows);
    scanA_kernel<<<NBLK, SCAN_BS>>>();
    scanC_kernel<<<NBLK, SCAN_BS>>>();
    scatter_kernel<<<ebl4, 256>>>(erows, ecols, evals);

    // Y[k][n] = (S_k @ Xh)[n]; warp per node (R7 best-measured form)
    int ablocks = (N_NODES * 32 + 255) / 256;
    accum_kernel<<<ablocks, 256>>>();

    // out = concat_k(Y_k) @ W + bias on tensor cores
    gemm_tc_kernel<<<(N_NODES + 63) / 64, 256>>>(bias, out);
}